// round 1
// baseline (speedup 1.0000x reference)
#include <cuda_runtime.h>
#include <cstdint>

#define HH 512
#define WW 512
#define CC 256
#define KS 11
#define OO 502
#define TILE_OX 64
#define TILE_OY 32
#define SMW 74          // TILE_OX + KS - 1
#define SMH 42          // TILE_OY + KS - 1
#define PITCH 75        // odd pitch -> <=2-way LDS bank conflicts
#define NSPLIT 4
#define CPS (CC / NSPLIT)

// Deterministic per-split partial sums (no atomics).
__device__ float g_partial[NSPLIT][OO * OO];

__global__ __launch_bounds__(128) void conv_kernel(const float* __restrict__ x,
                                                   const float* __restrict__ kern) {
    __shared__ float tile[SMH * PITCH];
    __shared__ float2 k2s[128];   // 121 used (packed (k,k) pairs)

    const int tx  = threadIdx.x;          // 0..7   -> 8 output cols each
    const int ty  = threadIdx.y;          // 0..15  -> 2 output rows each
    const int tid = ty * 8 + tx;
    const int ox0 = blockIdx.x * TILE_OX;
    const int oy0 = blockIdx.y * TILE_OY;
    const int c0  = blockIdx.z * CPS;

    // 8 packed accumulators: lane.x = output row r0, lane.y = row r0+1
    unsigned long long acc[8];
#pragma unroll
    for (int j = 0; j < 8; j++) acc[j] = 0ULL;

    const float* xb0 = x;
    const float* xb1 = x + (size_t)CC * HH * WW;

    for (int ci = 0; ci < CPS; ci++) {
        const int c = c0 + ci;
        const float* p0 = xb0 + (size_t)c * HH * WW;
        const float* p1 = xb1 + (size_t)c * HH * WW;

        __syncthreads();
        // Stage input tile (batch-sum fused), zero-padded at the edges.
        for (int idx = tid; idx < SMH * SMW; idx += 128) {
            const int r  = idx / SMW;
            const int cc = idx - r * SMW;
            const int gy = oy0 + r;
            const int gx = ox0 + cc;
            float v = 0.0f;
            if (gy < HH && gx < WW) {
                const int off = gy * WW + gx;
                v = p0[off] + p1[off];
            }
            tile[r * PITCH + cc] = v;
        }
        // Stage packed kernel weights for this channel.
        if (tid < 121) {
            const float v = kern[c * 121 + tid];
            k2s[tid] = make_float2(v, v);
        }
        __syncthreads();

        const float* rowbase = &tile[(2 * ty) * PITCH + 8 * tx];

        float cur[18], nxt[18];
#pragma unroll
        for (int t = 0; t < 18; t++) cur[t] = rowbase[t];

#pragma unroll
        for (int kh = 0; kh < KS; kh++) {
            const float* rb = rowbase + (kh + 1) * PITCH;
#pragma unroll
            for (int t = 0; t < 18; t++) nxt[t] = rb[t];

            // Pack the two row windows into f32x2 once per kh; reuse for all kw,j.
            unsigned long long px[18];
#pragma unroll
            for (int t = 0; t < 18; t++)
                asm("mov.b64 %0, {%1, %2};" : "=l"(px[t]) : "f"(cur[t]), "f"(nxt[t]));

#pragma unroll
            for (int kw = 0; kw < KS; kw++) {
                const unsigned long long kv =
                    *reinterpret_cast<const unsigned long long*>(&k2s[kh * KS + kw]);
#pragma unroll
                for (int j = 0; j < 8; j++)
                    asm("fma.rn.f32x2 %0, %1, %2, %0;"
                        : "+l"(acc[j]) : "l"(px[kw + j]), "l"(kv));
            }
#pragma unroll
            for (int t = 0; t < 18; t++) cur[t] = nxt[t];
        }
    }

    // Store the 2x8 microtile into this split's partial plane.
    const int r0 = oy0 + 2 * ty;
    const int r1 = r0 + 1;
#pragma unroll
    for (int j = 0; j < 8; j++) {
        const int oxp = ox0 + 8 * tx + j;
        if (oxp < OO) {
            float lo, hi;
            asm("mov.b64 {%0, %1}, %2;" : "=f"(lo), "=f"(hi) : "l"(acc[j]));
            if (r0 < OO) g_partial[blockIdx.z][r0 * OO + oxp] = lo;
            if (r1 < OO) g_partial[blockIdx.z][r1 * OO + oxp] = hi;
        }
    }
}

__global__ void finalize_kernel(const float* __restrict__ bias, float* __restrict__ out) {
    const int i = blockIdx.x * blockDim.x + threadIdx.x;
    if (i < OO * OO) {
        const float s = g_partial[0][i] + g_partial[1][i] +
                        g_partial[2][i] + g_partial[3][i] + bias[0];
        out[i] = s;               // batch 0
        out[OO * OO + i] = s;     // batch 1 (broadcast)
    }
}

extern "C" void kernel_launch(void* const* d_in, const int* in_sizes, int n_in,
                              void* d_out, int out_size) {
    const float* x    = (const float*)d_in[0];   // [2,256,512,512]
    const float* kern = (const float*)d_in[1];   // [1,256,11,11]
    const float* bias = (const float*)d_in[2];   // [1]
    float* out = (float*)d_out;                  // [2,1,502,502]

    dim3 block(8, 16, 1);                        // 128 threads
    dim3 grid(8, 16, NSPLIT);                    // 8*64=512 >= 502, 16*32=512 >= 502
    conv_kernel<<<grid, block>>>(x, kern);

    finalize_kernel<<<(OO * OO + 255) / 256, 256>>>(bias, out);
}